// round 16
// baseline (speedup 1.0000x reference)
#include <cuda_runtime.h>
#include <cuda_bf16.h>

// RNN: B=8192, T=2048, I=2, H=20
//   h_{t+1} = tanh(x_t @ W_ih^T + b_ih + b_hh + h_t @ W_hh^T)
//   out = h_T @ fc_w^T + fc_b ; h_state = h_T
//
// R15: R13's rotation-shfl design with TWO rows per lane sharing one W slab.
// 4 lanes per row-pair, 8 pairs/warp -> 16 rows/warp, 512 single-warp CTAs.
// Per lane-step: 30 SHFL + 2x(45 fma2 + 20 FFMA) + 2x tanh-block, i.e. the
// fixed exchange/activation machinery amortized over 2 independent
// recurrence chains (within-warp ILP replaces the cross-warp overlap that
// 0.87 warps/SMSP cannot provide).
//  * k-permutation pairing: 8 u64 pairs + 4 scalars per source rotation.
//  * W, b pre-scaled by 2*log2e -> tanh = ex2 + add + rcp + fma.
//  * W shared by both rows: ~125 const regs, ~190 total (no spills).

#define BB 8192
#define TT 2048
#define HH 20
#define UPL 5     // units per lane
#define PPW 8     // row-pairs per warp
#define RPW 16    // rows per warp

typedef unsigned long long u64;

__device__ __forceinline__ u64 pack2(float lo, float hi) {
    u64 r; asm("mov.b64 %0, {%1, %2};" : "=l"(r) : "f"(lo), "f"(hi)); return r;
}
__device__ __forceinline__ float2 unpack2(u64 v) {
    float2 f; asm("mov.b64 {%0, %1}, %2;" : "=f"(f.x), "=f"(f.y) : "l"(v)); return f;
}
__device__ __forceinline__ u64 fma2(u64 a, u64 b, u64 c) {
    u64 d;
    asm("fma.rn.f32x2 %0, %1, %2, %3;" : "=l"(d) : "l"(a), "l"(b), "l"(c));
    return d;
}
// z' PRE-SCALED by 2*log2e: tanh = 1 - 2/(1 + 2^(z'))
__device__ __forceinline__ float tanh_scaled(float zp) {
    float e, r;
    asm("ex2.approx.f32 %0, %1;" : "=f"(e) : "f"(zp));
    asm("rcp.approx.f32 %0, %1;" : "=f"(r) : "f"(e + 1.0f));
    return fmaf(-2.0f, r, 1.0f);
}

__global__ __launch_bounds__(32)
void rnn_fused_kernel(const float* __restrict__ x,
                      const float* __restrict__ Wih,
                      const float* __restrict__ Whh,
                      const float* __restrict__ bih,
                      const float* __restrict__ bhh,
                      const float* __restrict__ fcw,
                      const float* __restrict__ fcb,
                      float* __restrict__ out) {
    const float S = 2.8853900817779268f;   // 2*log2(e)

    const int lane = (int)(threadIdx.x & 31u);
    const int p    = lane & 3;              // part: units 5p..5p+4
    const int pair = lane >> 2;             // row-pair within warp (0..7)
    const unsigned gbase = (unsigned)(lane & ~3);
    const unsigned FULL  = 0xFFFFFFFFu;

    const int rowA = (blockIdx.x * PPW + pair) * 2;   // two adjacent rows
    const int rowB = rowA + 1;

    // shfl source lanes for rotations d = 1..3
    const unsigned sl1 = gbase + (unsigned)((p + 1) & 3);
    const unsigned sl2 = gbase + (unsigned)((p + 2) & 3);
    const unsigned sl3 = gbase + (unsigned)((p + 3) & 3);

    // ---- shared per-lane constants (pre-scaled by S) ----
    // rotation d: columns from lane q=(p+d)&3: k = 5q..5q+4 as 2 pairs + 1 scalar
    u64   W2r[UPL][4][2];   // 40 u64 = 80 regs
    float Wsr[UPL][4];      // 20 regs
    u64   w01[UPL];         // 10 regs
    float b[UPL];           // 5 regs
#pragma unroll
    for (int u = 0; u < UPL; ++u) {
        const int j = p * UPL + u;
        b[u]   = S * (bih[j] + bhh[j]);
        w01[u] = pack2(S * Wih[2 * j], S * Wih[2 * j + 1]);
#pragma unroll
        for (int d = 0; d < 4; ++d) {
            const int q = (p + d) & 3;
            const float* wr = Whh + j * HH + 5 * q;
            W2r[u][d][0] = pack2(S * wr[0], S * wr[1]);
            W2r[u][d][1] = pack2(S * wr[2], S * wr[3]);
            Wsr[u][d]    = S * wr[4];
        }
    }

    // h state per row: 2 packed pairs + 1 scalar (units 5p..5p+4)
    u64 pA_A = 0ull, pB_A = 0ull;  float hS_A = 0.0f;
    u64 pA_B = 0ull, pB_B = 0ull;  float hS_B = 0.0f;
    float hA[UPL], hB[UPL];
#pragma unroll
    for (int u = 0; u < UPL; ++u) { hA[u] = 0.0f; hB[u] = 0.0f; }

    // x: [B, T, 2]; each lane loads BOTH its rows (group lanes share sectors)
    const ulonglong2* xrA =
        reinterpret_cast<const ulonglong2*>(x) + (size_t)rowA * (TT / 2);
    const ulonglong2* xrB = xrA + (TT / 2);
    ulonglong2 xaA = xrA[0], xbA = xrA[1];
    ulonglong2 xaB = xrB[0], xbB = xrB[1];
    const int NC = TT / 4;    // 512 chunks of 4 steps

    for (int c = 0; c < NC; ++c) {
        const int cn = (c + 1 < NC) ? (c + 1) : 0;   // branch-free prefetch
        const ulonglong2 xnaA = xrA[2 * cn], xnbA = xrA[2 * cn + 1];
        const ulonglong2 xnaB = xrB[2 * cn], xnbB = xrB[2 * cn + 1];
        u64 xsA[4] = { xaA.x, xaA.y, xbA.x, xbA.y };
        u64 xsB[4] = { xaB.x, xaB.y, xbB.x, xbB.y };

#pragma unroll
        for (int s = 0; s < 4; ++s) {
            // ---- exchange: own + 3 rotated sources, both rows (30 SHFL) ----
            u64 rAa[4], rBa[4];  float rSa[4];
            u64 rAb[4], rBb[4];  float rSb[4];
            rAa[0] = pA_A; rBa[0] = pB_A; rSa[0] = hS_A;
            rAb[0] = pA_B; rBb[0] = pB_B; rSb[0] = hS_B;
            rAa[1] = __shfl_sync(FULL, pA_A, sl1);
            rBa[1] = __shfl_sync(FULL, pB_A, sl1);
            rSa[1] = __shfl_sync(FULL, hS_A, sl1);
            rAb[1] = __shfl_sync(FULL, pA_B, sl1);
            rBb[1] = __shfl_sync(FULL, pB_B, sl1);
            rSb[1] = __shfl_sync(FULL, hS_B, sl1);
            rAa[2] = __shfl_sync(FULL, pA_A, sl2);
            rBa[2] = __shfl_sync(FULL, pB_A, sl2);
            rSa[2] = __shfl_sync(FULL, hS_A, sl2);
            rAb[2] = __shfl_sync(FULL, pA_B, sl2);
            rBb[2] = __shfl_sync(FULL, pB_B, sl2);
            rSb[2] = __shfl_sync(FULL, hS_B, sl2);
            rAa[3] = __shfl_sync(FULL, pA_A, sl3);
            rBa[3] = __shfl_sync(FULL, pB_A, sl3);
            rSa[3] = __shfl_sync(FULL, hS_A, sl3);
            rAb[3] = __shfl_sync(FULL, pA_B, sl3);
            rBb[3] = __shfl_sync(FULL, pB_B, sl3);
            rSb[3] = __shfl_sync(FULL, hS_B, sl3);

            // ---- MAC both rows through the SAME W registers ----
            u64 accPA[UPL], accPB[UPL];
            float accSA[UPL], accSB[UPL];
#pragma unroll
            for (int u = 0; u < UPL; ++u) {
                accPA[u] = fma2(xsA[s], w01[u], 0ull);
                accPB[u] = fma2(xsB[s], w01[u], 0ull);
                accSA[u] = b[u];
                accSB[u] = b[u];
            }
#pragma unroll
            for (int d = 0; d < 4; ++d) {
#pragma unroll
                for (int u = 0; u < UPL; ++u) {
                    accPA[u] = fma2(rAa[d], W2r[u][d][0], accPA[u]);
                    accPB[u] = fma2(rAb[d], W2r[u][d][0], accPB[u]);
                    accPA[u] = fma2(rBa[d], W2r[u][d][1], accPA[u]);
                    accPB[u] = fma2(rBb[d], W2r[u][d][1], accPB[u]);
                    accSA[u] = fmaf(rSa[d], Wsr[u][d], accSA[u]);
                    accSB[u] = fmaf(rSb[d], Wsr[u][d], accSB[u]);
                }
            }

            // ---- activation ----
#pragma unroll
            for (int u = 0; u < UPL; ++u) {
                const float2 fa = unpack2(accPA[u]);
                const float2 fb = unpack2(accPB[u]);
                hA[u] = tanh_scaled((fa.x + fa.y) + accSA[u]);
                hB[u] = tanh_scaled((fb.x + fb.y) + accSB[u]);
            }
            pA_A = pack2(hA[0], hA[1]);  pB_A = pack2(hA[2], hA[3]);  hS_A = hA[4];
            pA_B = pack2(hB[0], hB[1]);  pB_B = pack2(hB[2], hB[3]);  hS_B = hB[4];
        }
        xaA = xnaA; xbA = xnbA;
        xaB = xnaB; xbB = xnbB;
    }

    // ---- epilogue: h_state then fc head (both rows) ----
    float* hs = out + BB;   // h_state [1, B, H] right after out [B, 1]
#pragma unroll
    for (int u = 0; u < UPL; ++u) {
        hs[(size_t)rowA * HH + p * UPL + u] = hA[u];
        hs[(size_t)rowB * HH + p * UPL + u] = hB[u];
    }

    float psA = 0.0f, psB = 0.0f;
#pragma unroll
    for (int u = 0; u < UPL; ++u) {
        const float w = fcw[p * UPL + u];
        psA = fmaf(hA[u], w, psA);
        psB = fmaf(hB[u], w, psB);
    }
    psA += __shfl_xor_sync(FULL, psA, 1);
    psA += __shfl_xor_sync(FULL, psA, 2);
    psB += __shfl_xor_sync(FULL, psB, 1);
    psB += __shfl_xor_sync(FULL, psB, 2);
    if (p == 0) {
        out[rowA] = psA + fcb[0];
        out[rowB] = psB + fcb[0];
    }
}

extern "C" void kernel_launch(void* const* d_in, const int* in_sizes, int n_in,
                              void* d_out, int out_size) {
    const float* x   = (const float*)d_in[0];
    const float* Wih = (const float*)d_in[1];
    const float* Whh = (const float*)d_in[2];
    const float* bih = (const float*)d_in[3];
    const float* bhh = (const float*)d_in[4];
    const float* fcw = (const float*)d_in[5];
    const float* fcb = (const float*)d_in[6];
    float* out = (float*)d_out;

    rnn_fused_kernel<<<BB / RPW, 32>>>(x, Wih, Whh, bih, bhh, fcw, fcb, out);
}

// round 17
// speedup vs baseline: 1.1707x; 1.1707x over previous
#include <cuda_runtime.h>
#include <cuda_bf16.h>

// RNN: B=8192, T=2048, I=2, H=20
//   h_{t+1} = tanh(x_t @ W_ih^T + b_ih + b_hh + h_t @ W_hh^T)
//   out = h_T @ fc_w^T + fc_b ; h_state = h_T
//
// R17 = R13 (proven best topology: 4 lanes/row, 5 units/lane, 8 rows/warp,
// 1024 warps = 1.73/SMSP) with the exchange cut 15 -> 8 SHFLs:
//  * After tanh, lane p cross-packs its scalar h[4] with partner (xor-1
//    shfl + pack -> pC), then xor-2 shfl fetches the other pair's pC2.
//    All four lanes' fifth-units now travel in 2 u64s.
//  * Exchange/step: 6 rotation shfls (pA,pB x 3 sources) + 2 xor shfls.
//  * MAC is pure fma2: 11/unit (x+bias, 8 rotation pairs, pC, pC2).
//    W pair-orderings for pC/pC2 are baked per-lane at init.
//  * W,b pre-scaled by 2*log2e -> tanh = ex2 + add + rcp + fma (unchanged).

#define BB 8192
#define TT 2048
#define HH 20
#define UPL 5     // units per lane
#define RPW 8     // rows per warp

typedef unsigned long long u64;

__device__ __forceinline__ u64 pack2(float lo, float hi) {
    u64 r; asm("mov.b64 %0, {%1, %2};" : "=l"(r) : "f"(lo), "f"(hi)); return r;
}
__device__ __forceinline__ float2 unpack2(u64 v) {
    float2 f; asm("mov.b64 {%0, %1}, %2;" : "=f"(f.x), "=f"(f.y) : "l"(v)); return f;
}
__device__ __forceinline__ u64 fma2(u64 a, u64 b, u64 c) {
    u64 d;
    asm("fma.rn.f32x2 %0, %1, %2, %3;" : "=l"(d) : "l"(a), "l"(b), "l"(c));
    return d;
}
// z' PRE-SCALED by 2*log2e: tanh = 1 - 2/(1 + 2^(z'))
__device__ __forceinline__ float tanh_scaled(float zp) {
    float e, r;
    asm("ex2.approx.f32 %0, %1;" : "=f"(e) : "f"(zp));
    asm("rcp.approx.f32 %0, %1;" : "=f"(r) : "f"(e + 1.0f));
    return fmaf(-2.0f, r, 1.0f);
}

__global__ __launch_bounds__(32)
void rnn_fused_kernel(const float* __restrict__ x,
                      const float* __restrict__ Wih,
                      const float* __restrict__ Whh,
                      const float* __restrict__ bih,
                      const float* __restrict__ bhh,
                      const float* __restrict__ fcw,
                      const float* __restrict__ fcb,
                      float* __restrict__ out) {
    const float S = 2.8853900817779268f;   // 2*log2(e)

    const int lane = (int)(threadIdx.x & 31u);
    const int p    = lane & 3;              // part: units 5p..5p+4
    const int grp  = lane >> 2;             // row within warp (0..7)
    const unsigned gbase = (unsigned)(lane & ~3);
    const unsigned FULL  = 0xFFFFFFFFu;

    const int row = blockIdx.x * RPW + grp;

    // shfl source lanes for rotations d = 1..3
    const unsigned sl1 = gbase + (unsigned)((p + 1) & 3);
    const unsigned sl2 = gbase + (unsigned)((p + 2) & 3);
    const unsigned sl3 = gbase + (unsigned)((p + 3) & 3);

    // ---- per-lane constants (pre-scaled by S) ----
    // rotation d: pairs (5q, 5q+1), (5q+2, 5q+3) from source lane q=(p+d)&3.
    // fifth units travel packed: pC  = (h4 of lane p,   h4 of lane p^1)
    //                            pC2 = (h4 of lane p^2, h4 of lane p^3)
    u64 W2r[UPL][4][2];   // 40 u64
    u64 WpC[UPL][2];      // 10 u64
    u64 w01[UPL];         // x weights (pair over I=2)
    u64 bias2[UPL];       // (S*(bih+bhh), 0)
#pragma unroll
    for (int u = 0; u < UPL; ++u) {
        const int j = p * UPL + u;
        bias2[u] = pack2(S * (bih[j] + bhh[j]), 0.0f);
        w01[u]   = pack2(S * Wih[2 * j], S * Wih[2 * j + 1]);
#pragma unroll
        for (int d = 0; d < 4; ++d) {
            const int q = (p + d) & 3;
            const float* wr = Whh + j * HH + 5 * q;
            W2r[u][d][0] = pack2(S * wr[0], S * wr[1]);
            W2r[u][d][1] = pack2(S * wr[2], S * wr[3]);
        }
        const float* wj = Whh + j * HH;
        WpC[u][0] = pack2(S * wj[5 * p + 4],        S * wj[5 * (p ^ 1) + 4]);
        WpC[u][1] = pack2(S * wj[5 * (p ^ 2) + 4],  S * wj[5 * (p ^ 3) + 4]);
    }

    // own h state: 2 packed pairs + 1 scalar, init 0
    u64 pA = 0ull, pB = 0ull;
    float hS = 0.0f;
    u64 pC = 0ull;         // cross-packed fifth units (this pair)
    float h[UPL];
#pragma unroll
    for (int u = 0; u < UPL; ++u) h[u] = 0.0f;

    // x: [B, T, 2]; each lane loads its OWN row (group lanes share sectors)
    const ulonglong2* xr2 =
        reinterpret_cast<const ulonglong2*>(x) + (size_t)row * (TT / 2);
    ulonglong2 xa = xr2[0];
    ulonglong2 xb = xr2[1];
    const int NC = TT / 4;    // 512 chunks of 4 steps

    for (int c = 0; c < NC; ++c) {
        const int cn = (c + 1 < NC) ? (c + 1) : 0;   // branch-free prefetch
        const ulonglong2 xna = xr2[2 * cn];
        const ulonglong2 xnb = xr2[2 * cn + 1];
        u64 xs[4] = { xa.x, xa.y, xb.x, xb.y };

#pragma unroll
        for (int s = 0; s < 4; ++s) {
            // ---- exchange: 6 rotation shfls + 1 xor shfl (pC2) ----
            u64 rA[4], rB[4];
            rA[0] = pA;  rB[0] = pB;
            rA[1] = __shfl_sync(FULL, pA, sl1);
            rB[1] = __shfl_sync(FULL, pB, sl1);
            rA[2] = __shfl_sync(FULL, pA, sl2);
            rB[2] = __shfl_sync(FULL, pB, sl2);
            rA[3] = __shfl_sync(FULL, pA, sl3);
            rB[3] = __shfl_sync(FULL, pB, sl3);
            const u64 pC2 = __shfl_xor_sync(FULL, pC, 2);

            // ---- MAC: 5 units x 11 fma2 (pure pair contraction) ----
            u64 acc[UPL];
#pragma unroll
            for (int u = 0; u < UPL; ++u)
                acc[u] = fma2(xs[s], w01[u], bias2[u]);
#pragma unroll
            for (int d = 0; d < 4; ++d)
#pragma unroll
                for (int u = 0; u < UPL; ++u) {
                    acc[u] = fma2(rA[d], W2r[u][d][0], acc[u]);
                    acc[u] = fma2(rB[d], W2r[u][d][1], acc[u]);
                }
#pragma unroll
            for (int u = 0; u < UPL; ++u) {
                acc[u] = fma2(pC,  WpC[u][0], acc[u]);
                acc[u] = fma2(pC2, WpC[u][1], acc[u]);
            }

            // ---- activation + repack (incl. cross-pack of fifth units) ----
#pragma unroll
            for (int u = 0; u < UPL; ++u) {
                const float2 f = unpack2(acc[u]);
                h[u] = tanh_scaled(f.x + f.y);
            }
            pA = pack2(h[0], h[1]);
            pB = pack2(h[2], h[3]);
            hS = h[4];
            const float ph4 = __shfl_xor_sync(FULL, hS, 1);
            pC = pack2(hS, ph4);
        }
        xa = xna;
        xb = xnb;
    }

    // ---- epilogue: h_state then fc head ----
    float* hs = out + BB;   // h_state [1, B, H] right after out [B, 1]
#pragma unroll
    for (int u = 0; u < UPL; ++u)
        hs[(size_t)row * HH + p * UPL + u] = h[u];

    float ps = 0.0f;
#pragma unroll
    for (int u = 0; u < UPL; ++u)
        ps = fmaf(h[u], fcw[p * UPL + u], ps);
    ps += __shfl_xor_sync(FULL, ps, 1);
    ps += __shfl_xor_sync(FULL, ps, 2);
    if (p == 0) out[row] = ps + fcb[0];
}

extern "C" void kernel_launch(void* const* d_in, const int* in_sizes, int n_in,
                              void* d_out, int out_size) {
    const float* x   = (const float*)d_in[0];
    const float* Wih = (const float*)d_in[1];
    const float* Whh = (const float*)d_in[2];
    const float* bih = (const float*)d_in[3];
    const float* bhh = (const float*)d_in[4];
    const float* fcw = (const float*)d_in[5];
    const float* fcb = (const float*)d_in[6];
    float* out = (float*)d_out;

    rnn_fused_kernel<<<BB / RPW, 32>>>(x, Wih, Whh, bih, bhh, fcw, fcb, out);
}